// round 1
// baseline (speedup 1.0000x reference)
#include <cuda_runtime.h>
#include <math.h>

// Shapes
#define BB 128      // batch
#define SS 64       // seq
#define UU 512      // units
#define VV 32000    // vocab
#define MM1 (BB*SS) // 8192 rows for the attention GEMM

// -------------------- scratch (no allocations allowed) --------------------
__device__ float g_score[MM1];          // pre-softmax scores
__device__ float g_xc[BB * 2 * UU];     // [x | context] concat, 128 x 1024
__device__ float g_g[BB * 3 * UU];      // GRU gates pre-activation, 128 x 1536
__device__ float g_state[BB * UU];      // GRU state, 128 x 512
__device__ float g_y[BB * UU];          // dense output, 128 x 512

// ============================================================
// Kernel 1: fused  score[m] = vb + sum_u tanh( (attn@W0)[m,u] + b0[u]+b1[u] ) * vW[u]
// Block: 64 rows (M-tile), loops N in chunks of 128, K in tiles of 32.
// 256 threads = 16x16, microtile 4 rows x 8 cols (stride-16 to stay bank-conflict free).
// ============================================================
__global__ __launch_bounds__(256)
void score_kernel(const float* __restrict__ attn, const float* __restrict__ W0,
                  const float* __restrict__ b0, const float* __restrict__ b1,
                  const float* __restrict__ vW, const float* __restrict__ vb) {
    __shared__ float As[64][33];
    __shared__ float Bs[32][128];
    __shared__ float sred[64][17];

    const int tid = threadIdx.x;
    const int tx = tid & 15;
    const int ty = tid >> 4;
    const int mbase = blockIdx.x * 64;

    float sAcc[4] = {0.f, 0.f, 0.f, 0.f};

    for (int nbase = 0; nbase < UU; nbase += 128) {
        float c[4][8];
        #pragma unroll
        for (int i = 0; i < 4; i++)
            #pragma unroll
            for (int j = 0; j < 8; j++) c[i][j] = 0.f;

        for (int kb = 0; kb < UU; kb += 32) {
            for (int t = tid; t < 64 * 32; t += 256)
                As[t >> 5][t & 31] = attn[(size_t)(mbase + (t >> 5)) * UU + kb + (t & 31)];
            for (int t = tid; t < 32 * 128; t += 256)
                Bs[t >> 7][t & 127] = W0[(size_t)(kb + (t >> 7)) * UU + nbase + (t & 127)];
            __syncthreads();

            #pragma unroll
            for (int kk = 0; kk < 32; kk++) {
                float a[4], bv[8];
                #pragma unroll
                for (int i = 0; i < 4; i++) a[i] = As[ty + 16 * i][kk];
                #pragma unroll
                for (int j = 0; j < 8; j++) bv[j] = Bs[kk][tx + 16 * j];
                #pragma unroll
                for (int i = 0; i < 4; i++)
                    #pragma unroll
                    for (int j = 0; j < 8; j++) c[i][j] += a[i] * bv[j];
            }
            __syncthreads();
        }

        // epilogue: tanh(+bias) then dot with vW, accumulate per-row
        #pragma unroll
        for (int j = 0; j < 8; j++) {
            int u = nbase + tx + 16 * j;
            float bias = b0[u] + b1[u];
            float w = vW[u];
            #pragma unroll
            for (int i = 0; i < 4; i++)
                sAcc[i] += tanhf(c[i][j] + bias) * w;
        }
    }

    #pragma unroll
    for (int i = 0; i < 4; i++) sred[ty + 16 * i][tx] = sAcc[i];
    __syncthreads();
    if (tid < 64) {
        float s = vb[0];
        #pragma unroll
        for (int t = 0; t < 16; t++) s += sred[tid][t];
        g_score[mbase + tid] = s;
    }
}

// ============================================================
// Kernel 2: per-batch softmax over 64 scores, context = sum_s attn[b,s,:]*alpha[s],
// embedding gather, and concat into g_xc. Also writes alpha to output.
// ============================================================
__global__ __launch_bounds__(256)
void ctx_kernel(const float* __restrict__ attn, const float* __restrict__ emb,
                const int* __restrict__ inputs, float* __restrict__ out_alpha) {
    __shared__ float sc[64];
    const int b = blockIdx.x;
    const int tid = threadIdx.x;

    if (tid < 64) sc[tid] = g_score[b * 64 + tid];
    __syncthreads();
    if (tid == 0) {
        float m = -1e30f;
        for (int s = 0; s < 64; s++) m = fmaxf(m, sc[s]);
        float sum = 0.f;
        for (int s = 0; s < 64; s++) { float e = expf(sc[s] - m); sc[s] = e; sum += e; }
        float inv = 1.f / sum;
        for (int s = 0; s < 64; s++) sc[s] *= inv;
    }
    __syncthreads();
    if (out_alpha != nullptr && tid < 64) out_alpha[b * 64 + tid] = sc[tid];

    const int row = inputs[b];
    for (int u = tid; u < UU; u += 256) {
        float acc = 0.f;
        #pragma unroll 8
        for (int s = 0; s < 64; s++)
            acc += attn[(size_t)(b * 64 + s) * UU + u] * sc[s];
        g_xc[b * (2 * UU) + UU + u] = acc;               // context half
        g_xc[b * (2 * UU) + u] = emb[(size_t)row * UU + u]; // embedding half
    }
}

// ============================================================
// Kernel 3: generic tiled GEMM  C = act(A[M,K] @ B[K,N] + bias[N])
// M-tile 64, N-tile 128, K-tile 32; 4x8 microtile stride-16. relu flag.
// ============================================================
__global__ __launch_bounds__(256)
void gemm_kernel(const float* __restrict__ A, const float* __restrict__ Bm,
                 const float* __restrict__ bias, float* __restrict__ C,
                 int M, int N, int K, int relu) {
    __shared__ float As[64][33];
    __shared__ float Bs[32][128];

    const int tid = threadIdx.x;
    const int tx = tid & 15;
    const int ty = tid >> 4;
    const int nbase = blockIdx.x * 128;
    const int mbase = blockIdx.y * 64;

    float c[4][8];
    #pragma unroll
    for (int i = 0; i < 4; i++)
        #pragma unroll
        for (int j = 0; j < 8; j++) c[i][j] = 0.f;

    for (int kb = 0; kb < K; kb += 32) {
        for (int t = tid; t < 64 * 32; t += 256)
            As[t >> 5][t & 31] = A[(size_t)(mbase + (t >> 5)) * K + kb + (t & 31)];
        for (int t = tid; t < 32 * 128; t += 256)
            Bs[t >> 7][t & 127] = Bm[(size_t)(kb + (t >> 7)) * N + nbase + (t & 127)];
        __syncthreads();

        #pragma unroll
        for (int kk = 0; kk < 32; kk++) {
            float a[4], bv[8];
            #pragma unroll
            for (int i = 0; i < 4; i++) a[i] = As[ty + 16 * i][kk];
            #pragma unroll
            for (int j = 0; j < 8; j++) bv[j] = Bs[kk][tx + 16 * j];
            #pragma unroll
            for (int i = 0; i < 4; i++)
                #pragma unroll
                for (int j = 0; j < 8; j++) c[i][j] += a[i] * bv[j];
        }
        __syncthreads();
    }

    #pragma unroll
    for (int j = 0; j < 8; j++) {
        int col = nbase + tx + 16 * j;
        float bv = bias[col];
        #pragma unroll
        for (int i = 0; i < 4; i++) {
            float v = c[i][j] + bv;
            if (relu) v = fmaxf(v, 0.f);
            C[(size_t)(mbase + ty + 16 * i) * N + col] = v;
        }
    }
}

// ============================================================
// Kernel 4: GRU elementwise. h==0 so rz/rr/rh are just gru_b[1] slices and
// state = (1-z)*hh exactly. g_g already contains xc@gru_k + gru_b[0].
// ============================================================
__global__ __launch_bounds__(256)
void gru_kernel(const float* __restrict__ gru_b, float* __restrict__ out_state) {
    const int i = blockIdx.x * blockDim.x + threadIdx.x;
    if (i >= BB * UU) return;
    const int b = i / UU;
    const int j = i % UU;
    const float* gb1 = gru_b + 3 * UU;  // gru_b[1] row

    float xz = g_g[b * 3 * UU + j]          + gb1[j];
    float xr = g_g[b * 3 * UU + UU + j]     + gb1[UU + j];
    float xh = g_g[b * 3 * UU + 2 * UU + j];
    float rh = gb1[2 * UU + j];

    float z = 1.f / (1.f + expf(-xz));
    float r = 1.f / (1.f + expf(-xr));
    float hh = tanhf(xh + r * rh);
    float st = (1.f - z) * hh;

    g_state[i] = st;
    if (out_state != nullptr) out_state[i] = st;
}

// ============================================================
// Launch
// ============================================================
extern "C" void kernel_launch(void* const* d_in, const int* in_sizes, int n_in,
                              void* d_out, int out_size) {
    const int*   inputs = (const int*)  d_in[0];
    const float* attn   = (const float*)d_in[1];
    const float* W0     = (const float*)d_in[2];
    const float* b0     = (const float*)d_in[3];
    // d_in[4] = W1   (dead: hidden0 == 0)
    const float* b1     = (const float*)d_in[5];
    const float* vW     = (const float*)d_in[6];
    const float* vb     = (const float*)d_in[7];
    const float* emb    = (const float*)d_in[8];
    const float* gru_k  = (const float*)d_in[9];
    // d_in[10] = gru_rk (dead: h == 0)
    const float* gru_b  = (const float*)d_in[11];
    const float* dW     = (const float*)d_in[12];
    const float* db     = (const float*)d_in[13];
    const float* oW     = (const float*)d_in[14];
    const float* ob     = (const float*)d_in[15];

    float* out = (float*)d_out;
    float* out_logits = out;
    float* out_state = nullptr;
    float* out_alpha = nullptr;
    if (out_size >= BB * VV + BB * UU + BB * SS) {
        out_state = out + (size_t)BB * VV;
        out_alpha = out_state + (size_t)BB * UU;
    }

    float *p_xc, *p_g, *p_state, *p_y;
    cudaGetSymbolAddress((void**)&p_xc, g_xc);
    cudaGetSymbolAddress((void**)&p_g, g_g);
    cudaGetSymbolAddress((void**)&p_state, g_state);
    cudaGetSymbolAddress((void**)&p_y, g_y);

    // 1) attention scores (fused GEMM + tanh + vW reduction)
    score_kernel<<<MM1 / 64, 256>>>(attn, W0, b0, b1, vW, vb);
    // 2) softmax + context + embedding gather + concat (+ alpha output)
    ctx_kernel<<<BB, 256>>>(attn, emb, inputs, out_alpha);
    // 3) GRU gates GEMM: [128,1024] @ [1024,1536] + gru_b[0]
    gemm_kernel<<<dim3(3 * UU / 128, BB / 64), 256>>>(p_xc, gru_k, gru_b, p_g, BB, 3 * UU, 2 * UU, 0);
    // 4) GRU nonlinearity (+ state output)
    gru_kernel<<<(BB * UU + 255) / 256, 256>>>(gru_b, out_state);
    // 5) dense: relu([128,512] @ [512,512] + db)
    gemm_kernel<<<dim3(UU / 128, BB / 64), 256>>>(p_state, dW, db, p_y, BB, UU, UU, 1);
    // 6) logits: [128,512] @ [512,32000] + ob  -> output
    gemm_kernel<<<dim3(VV / 128, BB / 64), 256>>>(p_y, oW, ob, out_logits, BB, VV, UU, 0);
}

// round 2
// speedup vs baseline: 2.6070x; 2.6070x over previous
#include <cuda_runtime.h>
#include <math.h>
#include <stdint.h>

// Shapes
#define BB 128      // batch
#define SS 64       // seq
#define UU 512      // units
#define VV 32000    // vocab
#define MM1 (BB*SS) // 8192 rows for the attention GEMM

// Tiling
#define Bb_M 64
#define Bb_N 128
#define Bb_K 32
#define SA 36    // As row stride (words): banks = 4*g + t, conflict-free
#define SB 136   // Bs row stride (words): banks = 8*t + g, conflict-free

// -------------------- scratch (no allocations allowed) --------------------
__device__ float g_score[MM1];          // pre-softmax scores
__device__ float g_xc[BB * 2 * UU];     // [x | context] concat, 128 x 1024
__device__ float g_g[BB * 3 * UU];      // GRU gates pre-activation, 128 x 1536
__device__ float g_state[BB * UU];      // GRU state, 128 x 512
__device__ float g_y[BB * UU];          // dense output, 128 x 512

// -------------------- tf32 helpers --------------------
__device__ __forceinline__ uint32_t f2tf32(float f) {
    uint32_t r;
    asm("cvt.rna.tf32.f32 %0, %1;" : "=r"(r) : "f"(f));
    return r;
}

__device__ __forceinline__ void mma_tf32(float c[4],
                                         uint32_t a0, uint32_t a1, uint32_t a2, uint32_t a3,
                                         uint32_t b0, uint32_t b1) {
    asm volatile(
        "mma.sync.aligned.m16n8k8.row.col.f32.tf32.tf32.f32 "
        "{%0,%1,%2,%3}, {%4,%5,%6,%7}, {%8,%9}, {%0,%1,%2,%3};"
        : "+f"(c[0]), "+f"(c[1]), "+f"(c[2]), "+f"(c[3])
        : "r"(a0), "r"(a1), "r"(a2), "r"(a3), "r"(b0), "r"(b1));
}

// Load A tile [64 x 32] from gmem (row-major, leading dim K) into As as tf32.
__device__ __forceinline__ void load_A_tile(uint32_t (*As)[SA], const float* __restrict__ A,
                                            int mbase, int kb, int K, int tid) {
    #pragma unroll
    for (int it = 0; it < 2; it++) {
        int i = tid + it * 256;          // 512 float4 slots
        int row = i >> 3;
        int c4 = (i & 7) * 4;
        float4 v = *reinterpret_cast<const float4*>(&A[(size_t)(mbase + row) * K + kb + c4]);
        As[row][c4 + 0] = f2tf32(v.x);
        As[row][c4 + 1] = f2tf32(v.y);
        As[row][c4 + 2] = f2tf32(v.z);
        As[row][c4 + 3] = f2tf32(v.w);
    }
}

// Load B tile [32 x 128] from gmem (row-major, leading dim N) into Bs as tf32.
__device__ __forceinline__ void load_B_tile(uint32_t (*Bs)[SB], const float* __restrict__ B,
                                            int kb, int nbase, int N, int tid) {
    #pragma unroll
    for (int it = 0; it < 4; it++) {
        int i = tid + it * 256;          // 1024 float4 slots
        int row = i >> 5;
        int c4 = (i & 31) * 4;
        float4 v = *reinterpret_cast<const float4*>(&B[(size_t)(kb + row) * N + nbase + c4]);
        Bs[row][c4 + 0] = f2tf32(v.x);
        Bs[row][c4 + 1] = f2tf32(v.y);
        Bs[row][c4 + 2] = f2tf32(v.z);
        Bs[row][c4 + 3] = f2tf32(v.w);
    }
}

// Inner product over one 64x128x32 tile staged in smem.
__device__ __forceinline__ void mma_tile(float acc[2][4][4],
                                         const uint32_t (*As)[SA], const uint32_t (*Bs)[SB],
                                         int wm, int wn, int g, int tg) {
    #pragma unroll
    for (int ks = 0; ks < Bb_K; ks += 8) {
        uint32_t af[2][4];
        uint32_t bf[4][2];
        #pragma unroll
        for (int mt = 0; mt < 2; mt++) {
            int r = wm * 32 + mt * 16 + g;
            af[mt][0] = As[r][ks + tg];
            af[mt][1] = As[r + 8][ks + tg];
            af[mt][2] = As[r][ks + tg + 4];
            af[mt][3] = As[r + 8][ks + tg + 4];
        }
        #pragma unroll
        for (int nt = 0; nt < 4; nt++) {
            int cidx = wn * 32 + nt * 8 + g;
            bf[nt][0] = Bs[ks + tg][cidx];
            bf[nt][1] = Bs[ks + tg + 4][cidx];
        }
        #pragma unroll
        for (int mt = 0; mt < 2; mt++)
            #pragma unroll
            for (int nt = 0; nt < 4; nt++)
                mma_tf32(acc[mt][nt], af[mt][0], af[mt][1], af[mt][2], af[mt][3],
                         bf[nt][0], bf[nt][1]);
    }
}

// ============================================================
// Kernel 1: fused score[m] = vb + sum_u tanh((attn@W0)[m,u] + b0[u]+b1[u]) * vW[u]
// ============================================================
__global__ __launch_bounds__(256)
void score_kernel(const float* __restrict__ attn, const float* __restrict__ W0,
                  const float* __restrict__ b0, const float* __restrict__ b1,
                  const float* __restrict__ vW, const float* __restrict__ vb) {
    __shared__ uint32_t As[Bb_M][SA];
    __shared__ uint32_t Bs[Bb_K][SB];
    __shared__ float sred[Bb_M][4];

    const int tid = threadIdx.x;
    const int warp = tid >> 5, lane = tid & 31;
    const int wm = warp >> 2, wn = warp & 3;
    const int g = lane >> 2, tg = lane & 3;
    const int mbase = blockIdx.x * Bb_M;

    float rs[2][2] = {{0.f, 0.f}, {0.f, 0.f}};  // [mt][half] row partial sums

    for (int nbase = 0; nbase < UU; nbase += Bb_N) {
        float acc[2][4][4];
        #pragma unroll
        for (int mt = 0; mt < 2; mt++)
            #pragma unroll
            for (int nt = 0; nt < 4; nt++)
                #pragma unroll
                for (int q = 0; q < 4; q++) acc[mt][nt][q] = 0.f;

        for (int kb = 0; kb < UU; kb += Bb_K) {
            load_A_tile(As, attn, mbase, kb, UU, tid);
            load_B_tile(Bs, W0, kb, nbase, UU, tid);
            __syncthreads();
            mma_tile(acc, As, Bs, wm, wn, g, tg);
            __syncthreads();
        }

        // Fused epilogue: tanh(+bias) * vW, accumulate per-row sums in registers
        #pragma unroll
        for (int nt = 0; nt < 4; nt++) {
            int col = nbase + wn * 32 + nt * 8 + 2 * tg;
            float bia0 = b0[col] + b1[col];
            float bia1 = b0[col + 1] + b1[col + 1];
            float w0v = vW[col];
            float w1v = vW[col + 1];
            #pragma unroll
            for (int mt = 0; mt < 2; mt++) {
                rs[mt][0] += tanhf(acc[mt][nt][0] + bia0) * w0v
                           + tanhf(acc[mt][nt][1] + bia1) * w1v;
                rs[mt][1] += tanhf(acc[mt][nt][2] + bia0) * w0v
                           + tanhf(acc[mt][nt][3] + bia1) * w1v;
            }
        }
    }

    // Reduce across tg lanes (same row group, different cols)
    #pragma unroll
    for (int mt = 0; mt < 2; mt++)
        #pragma unroll
        for (int h = 0; h < 2; h++) {
            rs[mt][h] += __shfl_xor_sync(0xffffffffu, rs[mt][h], 1);
            rs[mt][h] += __shfl_xor_sync(0xffffffffu, rs[mt][h], 2);
        }

    __syncthreads();
    if (tg == 0) {
        #pragma unroll
        for (int mt = 0; mt < 2; mt++)
            #pragma unroll
            for (int h = 0; h < 2; h++)
                sred[wm * 32 + mt * 16 + h * 8 + g][wn] = rs[mt][h];
    }
    __syncthreads();
    if (tid < Bb_M) {
        g_score[mbase + tid] = vb[0] + sred[tid][0] + sred[tid][1]
                             + sred[tid][2] + sred[tid][3];
    }
}

// ============================================================
// Kernel 2: softmax + context + embedding gather + concat (+ alpha output)
// ============================================================
__global__ __launch_bounds__(256)
void ctx_kernel(const float* __restrict__ attn, const float* __restrict__ emb,
                const int* __restrict__ inputs, float* __restrict__ out_alpha) {
    __shared__ float sc[64];
    const int b = blockIdx.x;
    const int tid = threadIdx.x;

    if (tid < 64) sc[tid] = g_score[b * 64 + tid];
    __syncthreads();
    if (tid == 0) {
        float m = -1e30f;
        for (int s = 0; s < 64; s++) m = fmaxf(m, sc[s]);
        float sum = 0.f;
        for (int s = 0; s < 64; s++) { float e = expf(sc[s] - m); sc[s] = e; sum += e; }
        float inv = 1.f / sum;
        for (int s = 0; s < 64; s++) sc[s] *= inv;
    }
    __syncthreads();
    if (out_alpha != nullptr && tid < 64) out_alpha[b * 64 + tid] = sc[tid];

    const int row = inputs[b];
    for (int u = tid; u < UU; u += 256) {
        float acc = 0.f;
        #pragma unroll 8
        for (int s = 0; s < 64; s++)
            acc += attn[(size_t)(b * 64 + s) * UU + u] * sc[s];
        g_xc[b * (2 * UU) + UU + u] = acc;                   // context half
        g_xc[b * (2 * UU) + u] = emb[(size_t)row * UU + u];  // embedding half
    }
}

// ============================================================
// Kernel 3: generic tf32 GEMM  C = act(A[M,K] @ B[K,N] + bias[N])
// ============================================================
__global__ __launch_bounds__(256)
void gemm_kernel(const float* __restrict__ A, const float* __restrict__ Bm,
                 const float* __restrict__ bias, float* __restrict__ C,
                 int M, int N, int K, int relu) {
    __shared__ uint32_t As[Bb_M][SA];
    __shared__ uint32_t Bs[Bb_K][SB];

    const int tid = threadIdx.x;
    const int warp = tid >> 5, lane = tid & 31;
    const int wm = warp >> 2, wn = warp & 3;
    const int g = lane >> 2, tg = lane & 3;
    const int nbase = blockIdx.x * Bb_N;
    const int mbase = blockIdx.y * Bb_M;

    float acc[2][4][4];
    #pragma unroll
    for (int mt = 0; mt < 2; mt++)
        #pragma unroll
        for (int nt = 0; nt < 4; nt++)
            #pragma unroll
            for (int q = 0; q < 4; q++) acc[mt][nt][q] = 0.f;

    for (int kb = 0; kb < K; kb += Bb_K) {
        load_A_tile(As, A, mbase, kb, K, tid);
        load_B_tile(Bs, Bm, kb, nbase, N, tid);
        __syncthreads();
        mma_tile(acc, As, Bs, wm, wn, g, tg);
        __syncthreads();
    }

    #pragma unroll
    for (int nt = 0; nt < 4; nt++) {
        int col = nbase + wn * 32 + nt * 8 + 2 * tg;
        float bv0 = bias[col], bv1 = bias[col + 1];
        #pragma unroll
        for (int mt = 0; mt < 2; mt++) {
            int row = mbase + wm * 32 + mt * 16 + g;
            float v0 = acc[mt][nt][0] + bv0;
            float v1 = acc[mt][nt][1] + bv1;
            float v2 = acc[mt][nt][2] + bv0;
            float v3 = acc[mt][nt][3] + bv1;
            if (relu) {
                v0 = fmaxf(v0, 0.f); v1 = fmaxf(v1, 0.f);
                v2 = fmaxf(v2, 0.f); v3 = fmaxf(v3, 0.f);
            }
            C[(size_t)row * N + col] = v0;
            C[(size_t)row * N + col + 1] = v1;
            C[(size_t)(row + 8) * N + col] = v2;
            C[(size_t)(row + 8) * N + col + 1] = v3;
        }
    }
}

// ============================================================
// Kernel 4: GRU elementwise (h == 0 simplifications are exact)
// ============================================================
__global__ __launch_bounds__(256)
void gru_kernel(const float* __restrict__ gru_b, float* __restrict__ out_state) {
    const int i = blockIdx.x * blockDim.x + threadIdx.x;
    if (i >= BB * UU) return;
    const int b = i / UU;
    const int j = i % UU;
    const float* gb1 = gru_b + 3 * UU;  // gru_b[1] row

    float xz = g_g[b * 3 * UU + j]          + gb1[j];
    float xr = g_g[b * 3 * UU + UU + j]     + gb1[UU + j];
    float xh = g_g[b * 3 * UU + 2 * UU + j];
    float rh = gb1[2 * UU + j];

    float z = 1.f / (1.f + expf(-xz));
    float r = 1.f / (1.f + expf(-xr));
    float hh = tanhf(xh + r * rh);
    float st = (1.f - z) * hh;

    g_state[i] = st;
    if (out_state != nullptr) out_state[i] = st;
}

// ============================================================
// Launch
// ============================================================
extern "C" void kernel_launch(void* const* d_in, const int* in_sizes, int n_in,
                              void* d_out, int out_size) {
    const int*   inputs = (const int*)  d_in[0];
    const float* attn   = (const float*)d_in[1];
    const float* W0     = (const float*)d_in[2];
    const float* b0     = (const float*)d_in[3];
    // d_in[4] = W1   (dead: hidden0 == 0)
    const float* b1     = (const float*)d_in[5];
    const float* vW     = (const float*)d_in[6];
    const float* vb     = (const float*)d_in[7];
    const float* emb    = (const float*)d_in[8];
    const float* gru_k  = (const float*)d_in[9];
    // d_in[10] = gru_rk (dead: h == 0)
    const float* gru_b  = (const float*)d_in[11];
    const float* dW     = (const float*)d_in[12];
    const float* db     = (const float*)d_in[13];
    const float* oW     = (const float*)d_in[14];
    const float* ob     = (const float*)d_in[15];

    float* out = (float*)d_out;
    float* out_logits = out;
    float* out_state = nullptr;
    float* out_alpha = nullptr;
    if (out_size >= BB * VV + BB * UU + BB * SS) {
        out_state = out + (size_t)BB * VV;
        out_alpha = out_state + (size_t)BB * UU;
    }

    float *p_xc, *p_g, *p_state, *p_y;
    cudaGetSymbolAddress((void**)&p_xc, g_xc);
    cudaGetSymbolAddress((void**)&p_g, g_g);
    cudaGetSymbolAddress((void**)&p_state, g_state);
    cudaGetSymbolAddress((void**)&p_y, g_y);

    // 1) attention scores (tf32 mma + fused tanh/vW reduction)
    score_kernel<<<MM1 / Bb_M, 256>>>(attn, W0, b0, b1, vW, vb);
    // 2) softmax + context + embedding gather + concat (+ alpha output)
    ctx_kernel<<<BB, 256>>>(attn, emb, inputs, out_alpha);
    // 3) GRU gates GEMM: [128,1024] @ [1024,1536] + gru_b[0]
    gemm_kernel<<<dim3(3 * UU / Bb_N, BB / Bb_M), 256>>>(p_xc, gru_k, gru_b, p_g, BB, 3 * UU, 2 * UU, 0);
    // 4) GRU nonlinearity (+ state output)
    gru_kernel<<<(BB * UU + 255) / 256, 256>>>(gru_b, out_state);
    // 5) dense: relu([128,512] @ [512,512] + db)
    gemm_kernel<<<dim3(UU / Bb_N, BB / Bb_M), 256>>>(p_state, dW, db, p_y, BB, UU, UU, 1);
    // 6) logits: [128,512] @ [512,32000] + ob -> output
    gemm_kernel<<<dim3(VV / Bb_N, BB / Bb_M), 256>>>(p_y, oW, ob, out_logits, BB, VV, UU, 0);
}

// round 3
// speedup vs baseline: 4.3053x; 1.6515x over previous
#include <cuda_runtime.h>
#include <math.h>
#include <stdint.h>

// Shapes
#define BB 128      // batch
#define SS 64       // seq
#define UU 512      // units
#define VV 32000    // vocab
#define MM1 (BB*SS) // 8192 rows for the attention GEMM

#define SA 36       // As row stride (words): banks = 4g + tg, conflict-free

// -------------------- scratch (no allocations allowed) --------------------
__device__ float g_score[MM1];
__device__ float g_xc[BB * 2 * UU];
__device__ float g_g[BB * 3 * UU];
__device__ float g_state[BB * UU];
__device__ float g_y[BB * UU];

// -------------------- tf32 helpers --------------------
__device__ __forceinline__ uint32_t f2tf32(float f) {
    uint32_t r;
    asm("cvt.rna.tf32.f32 %0, %1;" : "=r"(r) : "f"(f));
    return r;
}

__device__ __forceinline__ void mma_tf32(float c[4],
                                         uint32_t a0, uint32_t a1, uint32_t a2, uint32_t a3,
                                         uint32_t b0, uint32_t b1) {
    asm volatile(
        "mma.sync.aligned.m16n8k8.row.col.f32.tf32.tf32.f32 "
        "{%0,%1,%2,%3}, {%4,%5,%6,%7}, {%8,%9}, {%0,%1,%2,%3};"
        : "+f"(c[0]), "+f"(c[1]), "+f"(c[2]), "+f"(c[3])
        : "r"(a0), "r"(a1), "r"(a2), "r"(a3), "r"(b0), "r"(b1));
}

// ---------- staged loads: gmem -> regs, regs -> smem (tf32 convert) ----------
// A tile: 64 rows x 32 cols fp32, 2 float4 per thread (256 threads).
__device__ __forceinline__ void ldgA(float4 (&ar)[2], const float* __restrict__ A,
                                     int mbase, int kb, int K, int tid) {
    #pragma unroll
    for (int it = 0; it < 2; it++) {
        int i = tid + it * 256;
        ar[it] = *reinterpret_cast<const float4*>(
            &A[(size_t)(mbase + (i >> 3)) * K + kb + (i & 7) * 4]);
    }
}
__device__ __forceinline__ void stsA(uint32_t (*As)[SA], const float4 (&ar)[2], int tid) {
    #pragma unroll
    for (int it = 0; it < 2; it++) {
        int i = tid + it * 256;
        int row = i >> 3, c = (i & 7) * 4;
        As[row][c + 0] = f2tf32(ar[it].x);
        As[row][c + 1] = f2tf32(ar[it].y);
        As[row][c + 2] = f2tf32(ar[it].z);
        As[row][c + 3] = f2tf32(ar[it].w);
    }
}
// B tile: 32 rows x BN cols, BN = 32*NT, NT float4 per thread.
template<int NT>
__device__ __forceinline__ void ldgB(float4 (&br)[NT], const float* __restrict__ B,
                                     int kb, int nbase, int N, int tid) {
    #pragma unroll
    for (int it = 0; it < NT; it++) {
        int i = tid + it * 256;
        int row = i / (8 * NT), c = (i % (8 * NT)) * 4;
        br[it] = *reinterpret_cast<const float4*>(
            &B[(size_t)(kb + row) * N + nbase + c]);
    }
}
template<int NT, int SB>
__device__ __forceinline__ void stsB(uint32_t (*Bs)[SB], const float4 (&br)[NT], int tid) {
    #pragma unroll
    for (int it = 0; it < NT; it++) {
        int i = tid + it * 256;
        int row = i / (8 * NT), c = (i % (8 * NT)) * 4;
        Bs[row][c + 0] = f2tf32(br[it].x);
        Bs[row][c + 1] = f2tf32(br[it].y);
        Bs[row][c + 2] = f2tf32(br[it].z);
        Bs[row][c + 3] = f2tf32(br[it].w);
    }
}

// Inner product over one 64 x BN x 32 tile in smem.
template<int NT, int SB>
__device__ __forceinline__ void mma_tile(float (&acc)[2][NT][4],
                                         const uint32_t (*As)[SA], const uint32_t (*Bs)[SB],
                                         int wm, int wn, int g, int tg) {
    #pragma unroll
    for (int ks = 0; ks < 32; ks += 8) {
        uint32_t af[2][4];
        uint32_t bf[NT][2];
        #pragma unroll
        for (int mt = 0; mt < 2; mt++) {
            int r = wm * 32 + mt * 16 + g;
            af[mt][0] = As[r][ks + tg];
            af[mt][1] = As[r + 8][ks + tg];
            af[mt][2] = As[r][ks + tg + 4];
            af[mt][3] = As[r + 8][ks + tg + 4];
        }
        #pragma unroll
        for (int nt = 0; nt < NT; nt++) {
            int cidx = wn * (8 * NT) + nt * 8 + g;
            bf[nt][0] = Bs[ks + tg][cidx];
            bf[nt][1] = Bs[ks + tg + 4][cidx];
        }
        #pragma unroll
        for (int mt = 0; mt < 2; mt++)
            #pragma unroll
            for (int nt = 0; nt < NT; nt++)
                mma_tf32(acc[mt][nt], af[mt][0], af[mt][1], af[mt][2], af[mt][3],
                         bf[nt][0], bf[nt][1]);
    }
}

// ============================================================
// Generic tf32 GEMM: C = act(A[M,K] @ B[K,N] + bias[N])
// BM=64, BN=32*NT, BK=32, double-buffered, 1 sync per K-tile.
// NT=4 -> BN=128 (SB=136), NT=2 -> BN=64 (SB=72); both strides ≡ 8 mod 32.
// ============================================================
template<int NT, int SB>
__global__ __launch_bounds__(256)
void gemm_t(const float* __restrict__ A, const float* __restrict__ Bm,
            const float* __restrict__ bias, float* __restrict__ C,
            int M, int N, int K, int relu) {
    extern __shared__ uint32_t smem[];
    uint32_t (*As)[64][SA] = reinterpret_cast<uint32_t (*)[64][SA]>(smem);
    uint32_t (*Bs)[32][SB] = reinterpret_cast<uint32_t (*)[32][SB]>(smem + 2 * 64 * SA);

    const int tid = threadIdx.x;
    const int warp = tid >> 5, lane = tid & 31;
    const int wm = warp >> 2, wn = warp & 3;
    const int g = lane >> 2, tg = lane & 3;
    const int nbase = blockIdx.x * (32 * NT);
    const int mbase = blockIdx.y * 64;

    float acc[2][NT][4];
    #pragma unroll
    for (int mt = 0; mt < 2; mt++)
        #pragma unroll
        for (int nt = 0; nt < NT; nt++)
            #pragma unroll
            for (int q = 0; q < 4; q++) acc[mt][nt][q] = 0.f;

    const int T = K / 32;
    float4 ar[2];
    float4 br[NT];

    ldgA(ar, A, mbase, 0, K, tid);
    ldgB<NT>(br, Bm, 0, nbase, N, tid);
    stsA(As[0], ar, tid);
    stsB<NT, SB>(Bs[0], br, tid);
    __syncthreads();

    for (int t = 0; t < T; t++) {
        int cur = t & 1, nxt = cur ^ 1;
        if (t + 1 < T) {
            ldgA(ar, A, mbase, (t + 1) * 32, K, tid);
            ldgB<NT>(br, Bm, (t + 1) * 32, nbase, N, tid);
        }
        mma_tile<NT, SB>(acc, As[cur], Bs[cur], wm, wn, g, tg);
        if (t + 1 < T) {
            stsA(As[nxt], ar, tid);
            stsB<NT, SB>(Bs[nxt], br, tid);
            __syncthreads();
        }
    }

    #pragma unroll
    for (int nt = 0; nt < NT; nt++) {
        int col = nbase + wn * (8 * NT) + nt * 8 + 2 * tg;
        float bv0 = bias[col], bv1 = bias[col + 1];
        #pragma unroll
        for (int mt = 0; mt < 2; mt++) {
            int row = mbase + wm * 32 + mt * 16 + g;
            float2 v01 = make_float2(acc[mt][nt][0] + bv0, acc[mt][nt][1] + bv1);
            float2 v23 = make_float2(acc[mt][nt][2] + bv0, acc[mt][nt][3] + bv1);
            if (relu) {
                v01.x = fmaxf(v01.x, 0.f); v01.y = fmaxf(v01.y, 0.f);
                v23.x = fmaxf(v23.x, 0.f); v23.y = fmaxf(v23.y, 0.f);
            }
            *reinterpret_cast<float2*>(&C[(size_t)row * N + col]) = v01;
            *reinterpret_cast<float2*>(&C[(size_t)(row + 8) * N + col]) = v23;
        }
    }
}

// ============================================================
// Kernel 1: fused score[m] = vb + sum_u tanh((attn@W0)[m,u] + b0[u]+b1[u]) * vW[u]
// Same pipelined mainloop (NT=4), epilogue kept in registers.
// ============================================================
__global__ __launch_bounds__(256)
void score_kernel(const float* __restrict__ attn, const float* __restrict__ W0,
                  const float* __restrict__ b0, const float* __restrict__ b1,
                  const float* __restrict__ vW, const float* __restrict__ vb) {
    constexpr int SB = 136;
    extern __shared__ uint32_t smem[];
    uint32_t (*As)[64][SA] = reinterpret_cast<uint32_t (*)[64][SA]>(smem);
    uint32_t (*Bs)[32][SB] = reinterpret_cast<uint32_t (*)[32][SB]>(smem + 2 * 64 * SA);
    float (*sred)[4] = reinterpret_cast<float (*)[4]>(smem + 2 * 64 * SA + 2 * 32 * SB);

    const int tid = threadIdx.x;
    const int warp = tid >> 5, lane = tid & 31;
    const int wm = warp >> 2, wn = warp & 3;
    const int g = lane >> 2, tg = lane & 3;
    const int mbase = blockIdx.x * 64;

    float rs[2][2] = {{0.f, 0.f}, {0.f, 0.f}};
    float4 ar[2];
    float4 br[4];

    for (int nbase = 0; nbase < UU; nbase += 128) {
        float acc[2][4][4];
        #pragma unroll
        for (int mt = 0; mt < 2; mt++)
            #pragma unroll
            for (int nt = 0; nt < 4; nt++)
                #pragma unroll
                for (int q = 0; q < 4; q++) acc[mt][nt][q] = 0.f;

        const int T = UU / 32;  // 16
        ldgA(ar, attn, mbase, 0, UU, tid);
        ldgB<4>(br, W0, 0, nbase, UU, tid);
        stsA(As[0], ar, tid);
        stsB<4, SB>(Bs[0], br, tid);
        __syncthreads();

        for (int t = 0; t < T; t++) {
            int cur = t & 1, nxt = cur ^ 1;
            if (t + 1 < T) {
                ldgA(ar, attn, mbase, (t + 1) * 32, UU, tid);
                ldgB<4>(br, W0, (t + 1) * 32, nbase, UU, tid);
            }
            mma_tile<4, SB>(acc, As[cur], Bs[cur], wm, wn, g, tg);
            if (t + 1 < T) {
                stsA(As[nxt], ar, tid);
                stsB<4, SB>(Bs[nxt], br, tid);
                __syncthreads();
            }
        }
        __syncthreads();  // everyone done reading both buffers before next nbase refills

        // fused epilogue: tanh(+bias) * vW, accumulate per-row sums in regs
        #pragma unroll
        for (int nt = 0; nt < 4; nt++) {
            int col = nbase + wn * 32 + nt * 8 + 2 * tg;
            float bia0 = b0[col] + b1[col];
            float bia1 = b0[col + 1] + b1[col + 1];
            float w0v = vW[col];
            float w1v = vW[col + 1];
            #pragma unroll
            for (int mt = 0; mt < 2; mt++) {
                rs[mt][0] += tanhf(acc[mt][nt][0] + bia0) * w0v
                           + tanhf(acc[mt][nt][1] + bia1) * w1v;
                rs[mt][1] += tanhf(acc[mt][nt][2] + bia0) * w0v
                           + tanhf(acc[mt][nt][3] + bia1) * w1v;
            }
        }
    }

    #pragma unroll
    for (int mt = 0; mt < 2; mt++)
        #pragma unroll
        for (int h = 0; h < 2; h++) {
            rs[mt][h] += __shfl_xor_sync(0xffffffffu, rs[mt][h], 1);
            rs[mt][h] += __shfl_xor_sync(0xffffffffu, rs[mt][h], 2);
        }

    __syncthreads();
    if (tg == 0) {
        #pragma unroll
        for (int mt = 0; mt < 2; mt++)
            #pragma unroll
            for (int h = 0; h < 2; h++)
                sred[wm * 32 + mt * 16 + h * 8 + g][wn] = rs[mt][h];
    }
    __syncthreads();
    if (tid < 64) {
        g_score[mbase + tid] = vb[0] + sred[tid][0] + sred[tid][1]
                             + sred[tid][2] + sred[tid][3];
    }
}

// ============================================================
// Kernel 2: softmax + context + embedding gather + concat (+ alpha output)
// ============================================================
__global__ __launch_bounds__(128)
void ctx_kernel(const float* __restrict__ attn, const float* __restrict__ emb,
                const int* __restrict__ inputs, float* __restrict__ out_alpha) {
    __shared__ float sc[64];
    const int b = blockIdx.x;
    const int tid = threadIdx.x;

    if (tid < 64) sc[tid] = g_score[b * 64 + tid];
    __syncthreads();
    if (tid == 0) {
        float m = -1e30f;
        for (int s = 0; s < 64; s++) m = fmaxf(m, sc[s]);
        float sum = 0.f;
        for (int s = 0; s < 64; s++) { float e = expf(sc[s] - m); sc[s] = e; sum += e; }
        float inv = 1.f / sum;
        for (int s = 0; s < 64; s++) sc[s] *= inv;
    }
    __syncthreads();
    if (out_alpha != nullptr && tid < 64) out_alpha[b * 64 + tid] = sc[tid];

    const int row = inputs[b];
    const float4* attn4 = reinterpret_cast<const float4*>(attn);
    const float4* emb4  = reinterpret_cast<const float4*>(emb);
    float4* xc4 = reinterpret_cast<float4*>(g_xc);

    float4 a = make_float4(0.f, 0.f, 0.f, 0.f);
    #pragma unroll 8
    for (int s = 0; s < 64; s++) {
        float4 t = attn4[(size_t)(b * 64 + s) * 128 + tid];
        float al = sc[s];
        a.x += t.x * al; a.y += t.y * al; a.z += t.z * al; a.w += t.w * al;
    }
    xc4[(size_t)b * 256 + 128 + tid] = a;                     // context half
    xc4[(size_t)b * 256 + tid] = emb4[(size_t)row * 128 + tid]; // embedding half
}

// ============================================================
// Kernel 4: GRU elementwise (h == 0 simplifications are exact)
// ============================================================
__global__ __launch_bounds__(256)
void gru_kernel(const float* __restrict__ gru_b, float* __restrict__ out_state) {
    const int i = blockIdx.x * blockDim.x + threadIdx.x;
    if (i >= BB * UU) return;
    const int b = i / UU;
    const int j = i % UU;
    const float* gb1 = gru_b + 3 * UU;

    float xz = g_g[b * 3 * UU + j]          + gb1[j];
    float xr = g_g[b * 3 * UU + UU + j]     + gb1[UU + j];
    float xh = g_g[b * 3 * UU + 2 * UU + j];
    float rh = gb1[2 * UU + j];

    float z = 1.f / (1.f + expf(-xz));
    float r = 1.f / (1.f + expf(-xr));
    float hh = tanhf(xh + r * rh);
    float st = (1.f - z) * hh;

    g_state[i] = st;
    if (out_state != nullptr) out_state[i] = st;
}

// ============================================================
// Launch
// ============================================================
extern "C" void kernel_launch(void* const* d_in, const int* in_sizes, int n_in,
                              void* d_out, int out_size) {
    const int*   inputs = (const int*)  d_in[0];
    const float* attn   = (const float*)d_in[1];
    const float* W0     = (const float*)d_in[2];
    const float* b0     = (const float*)d_in[3];
    // d_in[4] = W1   (dead: hidden0 == 0)
    const float* b1     = (const float*)d_in[5];
    const float* vW     = (const float*)d_in[6];
    const float* vb     = (const float*)d_in[7];
    const float* emb    = (const float*)d_in[8];
    const float* gru_k  = (const float*)d_in[9];
    // d_in[10] = gru_rk (dead: h == 0)
    const float* gru_b  = (const float*)d_in[11];
    const float* dW     = (const float*)d_in[12];
    const float* db     = (const float*)d_in[13];
    const float* oW     = (const float*)d_in[14];
    const float* ob     = (const float*)d_in[15];

    float* out = (float*)d_out;
    float* out_logits = out;
    float* out_state = nullptr;
    float* out_alpha = nullptr;
    if (out_size >= BB * VV + BB * UU + BB * SS) {
        out_state = out + (size_t)BB * VV;
        out_alpha = out_state + (size_t)BB * UU;
    }

    float *p_xc, *p_g, *p_state, *p_y;
    cudaGetSymbolAddress((void**)&p_xc, g_xc);
    cudaGetSymbolAddress((void**)&p_g, g_g);
    cudaGetSymbolAddress((void**)&p_state, g_state);
    cudaGetSymbolAddress((void**)&p_y, g_y);

    // Dynamic smem sizes
    const int smem128 = (2 * 64 * SA + 2 * 32 * 136) * 4;   // 53248 B
    const int smem64  = (2 * 64 * SA + 2 * 32 * 72) * 4;    // 36864 B
    const int smemSc  = smem128 + 64 * 4 * 4;               // + sred

    static bool attr_done = false;
    if (!attr_done) {
        cudaFuncSetAttribute(score_kernel, cudaFuncAttributeMaxDynamicSharedMemorySize, smemSc);
        cudaFuncSetAttribute(gemm_t<4, 136>, cudaFuncAttributeMaxDynamicSharedMemorySize, smem128);
        attr_done = true;
    }

    // 1) attention scores (tf32 mma, pipelined, fused tanh/vW reduction)
    score_kernel<<<MM1 / 64, 256, smemSc>>>(attn, W0, b0, b1, vW, vb);
    // 2) softmax + context + embedding gather + concat (+ alpha output)
    ctx_kernel<<<BB, 128>>>(attn, emb, inputs, out_alpha);
    // 3) GRU gates GEMM: [128,1024] @ [1024,1536] + gru_b[0]  (BN=64 -> 48 blocks)
    gemm_t<2, 72><<<dim3(3 * UU / 64, BB / 64), 256, smem64>>>(p_xc, gru_k, gru_b, p_g, BB, 3 * UU, 2 * UU, 0);
    // 4) GRU nonlinearity (+ state output)
    gru_kernel<<<(BB * UU + 255) / 256, 256>>>(gru_b, out_state);
    // 5) dense: relu([128,512] @ [512,512] + db)  (BN=64 -> 16 blocks)
    gemm_t<2, 72><<<dim3(UU / 64, BB / 64), 256, smem64>>>(p_state, dW, db, p_y, BB, UU, UU, 1);
    // 6) logits: [128,512] @ [512,32000] + ob -> output
    gemm_t<4, 136><<<dim3(VV / 128, BB / 64), 256, smem128>>>(p_y, oW, ob, out_logits, BB, VV, UU, 0);
}

// round 4
// speedup vs baseline: 4.5579x; 1.0587x over previous
#include <cuda_runtime.h>
#include <math.h>
#include <stdint.h>

// Shapes
#define BB 128      // batch
#define SS 64       // seq
#define UU 512      // units
#define VV 32000    // vocab
#define MM1 (BB*SS) // 8192 rows for the attention GEMM

#define SA 36       // As row stride (words): banks = 4g + tg, conflict-free

// -------------------- scratch (no allocations allowed) --------------------
__device__ float g_score[MM1];
__device__ float g_xc[BB * 2 * UU];
__device__ float g_g[BB * 3 * UU];
__device__ float g_state[BB * UU];
__device__ float g_y[BB * UU];

// -------------------- tf32 helpers --------------------
__device__ __forceinline__ uint32_t f2tf32(float f) {
    uint32_t r;
    asm("cvt.rna.tf32.f32 %0, %1;" : "=r"(r) : "f"(f));
    return r;
}

__device__ __forceinline__ void mma_tf32(float c[4],
                                         uint32_t a0, uint32_t a1, uint32_t a2, uint32_t a3,
                                         uint32_t b0, uint32_t b1) {
    asm volatile(
        "mma.sync.aligned.m16n8k8.row.col.f32.tf32.tf32.f32 "
        "{%0,%1,%2,%3}, {%4,%5,%6,%7}, {%8,%9}, {%0,%1,%2,%3};"
        : "+f"(c[0]), "+f"(c[1]), "+f"(c[2]), "+f"(c[3])
        : "r"(a0), "r"(a1), "r"(a2), "r"(a3), "r"(b0), "r"(b1));
}

// ---------- staged loads: gmem -> regs, regs -> smem (tf32 convert) ----------
// A tile: 64 rows x 32 cols fp32, 2 float4 per thread (256 threads).
__device__ __forceinline__ void ldgA(float4 (&ar)[2], const float* __restrict__ A,
                                     int mbase, int kb, int K, int tid) {
    #pragma unroll
    for (int it = 0; it < 2; it++) {
        int i = tid + it * 256;
        ar[it] = *reinterpret_cast<const float4*>(
            &A[(size_t)(mbase + (i >> 3)) * K + kb + (i & 7) * 4]);
    }
}
__device__ __forceinline__ void stsA(uint32_t (*As)[SA], const float4 (&ar)[2], int tid) {
    #pragma unroll
    for (int it = 0; it < 2; it++) {
        int i = tid + it * 256;
        int row = i >> 3, c = (i & 7) * 4;
        As[row][c + 0] = f2tf32(ar[it].x);
        As[row][c + 1] = f2tf32(ar[it].y);
        As[row][c + 2] = f2tf32(ar[it].z);
        As[row][c + 3] = f2tf32(ar[it].w);
    }
}
// B tile: 32 rows x BN cols, BN = 32*NT, NT float4 per thread.
template<int NT>
__device__ __forceinline__ void ldgB(float4 (&br)[NT], const float* __restrict__ B,
                                     int kb, int nbase, int N, int tid) {
    #pragma unroll
    for (int it = 0; it < NT; it++) {
        int i = tid + it * 256;
        int row = i / (8 * NT), c = (i % (8 * NT)) * 4;
        br[it] = *reinterpret_cast<const float4*>(
            &B[(size_t)(kb + row) * N + nbase + c]);
    }
}
template<int NT, int SB>
__device__ __forceinline__ void stsB(uint32_t (*Bs)[SB], const float4 (&br)[NT], int tid) {
    #pragma unroll
    for (int it = 0; it < NT; it++) {
        int i = tid + it * 256;
        int row = i / (8 * NT), c = (i % (8 * NT)) * 4;
        Bs[row][c + 0] = f2tf32(br[it].x);
        Bs[row][c + 1] = f2tf32(br[it].y);
        Bs[row][c + 2] = f2tf32(br[it].z);
        Bs[row][c + 3] = f2tf32(br[it].w);
    }
}

// Inner product over one 64 x BN x 32 tile in smem. Warp tile = 32 x (8*NT).
template<int NT, int SB>
__device__ __forceinline__ void mma_tile(float (&acc)[2][NT][4],
                                         const uint32_t (*As)[SA], const uint32_t (*Bs)[SB],
                                         int wm, int wn, int g, int tg) {
    #pragma unroll
    for (int ks = 0; ks < 32; ks += 8) {
        uint32_t af[2][4];
        uint32_t bf[NT][2];
        #pragma unroll
        for (int mt = 0; mt < 2; mt++) {
            int r = wm * 32 + mt * 16 + g;
            af[mt][0] = As[r][ks + tg];
            af[mt][1] = As[r + 8][ks + tg];
            af[mt][2] = As[r][ks + tg + 4];
            af[mt][3] = As[r + 8][ks + tg + 4];
        }
        #pragma unroll
        for (int nt = 0; nt < NT; nt++) {
            int cidx = wn * (8 * NT) + nt * 8 + g;
            bf[nt][0] = Bs[ks + tg][cidx];
            bf[nt][1] = Bs[ks + tg + 4][cidx];
        }
        #pragma unroll
        for (int mt = 0; mt < 2; mt++)
            #pragma unroll
            for (int nt = 0; nt < NT; nt++)
                mma_tf32(acc[mt][nt], af[mt][0], af[mt][1], af[mt][2], af[mt][3],
                         bf[nt][0], bf[nt][1]);
    }
}

// ============================================================
// Generic tf32 GEMM: C = act(A[M,K] @ B[K,N] + bias[N])
// BM=64, BN=32*NT, BK=32, double-buffered, 1 sync per K-tile.
// NT=2->BN=64(SB=72), NT=4->BN=128(SB=136), NT=8->BN=256(SB=264).
// ============================================================
template<int NT, int SB>
__global__ __launch_bounds__(256)
void gemm_t(const float* __restrict__ A, const float* __restrict__ Bm,
            const float* __restrict__ bias, float* __restrict__ C,
            int M, int N, int K, int relu) {
    extern __shared__ uint32_t smem[];
    uint32_t (*As)[64][SA] = reinterpret_cast<uint32_t (*)[64][SA]>(smem);
    uint32_t (*Bs)[32][SB] = reinterpret_cast<uint32_t (*)[32][SB]>(smem + 2 * 64 * SA);

    const int tid = threadIdx.x;
    const int warp = tid >> 5, lane = tid & 31;
    const int wm = warp >> 2, wn = warp & 3;
    const int g = lane >> 2, tg = lane & 3;
    const int nbase = blockIdx.x * (32 * NT);
    const int mbase = blockIdx.y * 64;

    float acc[2][NT][4];
    #pragma unroll
    for (int mt = 0; mt < 2; mt++)
        #pragma unroll
        for (int nt = 0; nt < NT; nt++)
            #pragma unroll
            for (int q = 0; q < 4; q++) acc[mt][nt][q] = 0.f;

    const int T = K / 32;
    float4 ar[2];
    float4 br[NT];

    ldgA(ar, A, mbase, 0, K, tid);
    ldgB<NT>(br, Bm, 0, nbase, N, tid);
    stsA(As[0], ar, tid);
    stsB<NT, SB>(Bs[0], br, tid);
    __syncthreads();

    for (int t = 0; t < T; t++) {
        int cur = t & 1, nxt = cur ^ 1;
        if (t + 1 < T) {
            ldgA(ar, A, mbase, (t + 1) * 32, K, tid);
            ldgB<NT>(br, Bm, (t + 1) * 32, nbase, N, tid);
        }
        mma_tile<NT, SB>(acc, As[cur], Bs[cur], wm, wn, g, tg);
        if (t + 1 < T) {
            stsA(As[nxt], ar, tid);
            stsB<NT, SB>(Bs[nxt], br, tid);
            __syncthreads();
        }
    }

    #pragma unroll
    for (int nt = 0; nt < NT; nt++) {
        int col = nbase + wn * (8 * NT) + nt * 8 + 2 * tg;
        float bv0 = bias[col], bv1 = bias[col + 1];
        #pragma unroll
        for (int mt = 0; mt < 2; mt++) {
            int row = mbase + wm * 32 + mt * 16 + g;
            float2 v01 = make_float2(acc[mt][nt][0] + bv0, acc[mt][nt][1] + bv1);
            float2 v23 = make_float2(acc[mt][nt][2] + bv0, acc[mt][nt][3] + bv1);
            if (relu) {
                v01.x = fmaxf(v01.x, 0.f); v01.y = fmaxf(v01.y, 0.f);
                v23.x = fmaxf(v23.x, 0.f); v23.y = fmaxf(v23.y, 0.f);
            }
            *reinterpret_cast<float2*>(&C[(size_t)row * N + col]) = v01;
            *reinterpret_cast<float2*>(&C[(size_t)(row + 8) * N + col]) = v23;
        }
    }
}

// ============================================================
// Kernel 1: fused score[m] = vb + sum_u tanh((attn@W0)[m,u] + b0[u]+b1[u]) * vW[u]
// NT=8 (BN=256) -> only 2 nbase passes; epilogue in registers.
// ============================================================
__global__ __launch_bounds__(256)
void score_kernel(const float* __restrict__ attn, const float* __restrict__ W0,
                  const float* __restrict__ b0, const float* __restrict__ b1,
                  const float* __restrict__ vW, const float* __restrict__ vb) {
    constexpr int NT = 8;
    constexpr int SB = 264;
    extern __shared__ uint32_t smem[];
    uint32_t (*As)[64][SA] = reinterpret_cast<uint32_t (*)[64][SA]>(smem);
    uint32_t (*Bs)[32][SB] = reinterpret_cast<uint32_t (*)[32][SB]>(smem + 2 * 64 * SA);
    float (*sred)[4] = reinterpret_cast<float (*)[4]>(smem + 2 * 64 * SA + 2 * 32 * SB);

    const int tid = threadIdx.x;
    const int warp = tid >> 5, lane = tid & 31;
    const int wm = warp >> 2, wn = warp & 3;
    const int g = lane >> 2, tg = lane & 3;
    const int mbase = blockIdx.x * 64;

    float rs[2][2] = {{0.f, 0.f}, {0.f, 0.f}};
    float4 ar[2];
    float4 br[NT];

    for (int nbase = 0; nbase < UU; nbase += 32 * NT) {
        float acc[2][NT][4];
        #pragma unroll
        for (int mt = 0; mt < 2; mt++)
            #pragma unroll
            for (int nt = 0; nt < NT; nt++)
                #pragma unroll
                for (int q = 0; q < 4; q++) acc[mt][nt][q] = 0.f;

        const int T = UU / 32;  // 16
        ldgA(ar, attn, mbase, 0, UU, tid);
        ldgB<NT>(br, W0, 0, nbase, UU, tid);
        stsA(As[0], ar, tid);
        stsB<NT, SB>(Bs[0], br, tid);
        __syncthreads();

        for (int t = 0; t < T; t++) {
            int cur = t & 1, nxt = cur ^ 1;
            if (t + 1 < T) {
                ldgA(ar, attn, mbase, (t + 1) * 32, UU, tid);
                ldgB<NT>(br, W0, (t + 1) * 32, nbase, UU, tid);
            }
            mma_tile<NT, SB>(acc, As[cur], Bs[cur], wm, wn, g, tg);
            if (t + 1 < T) {
                stsA(As[nxt], ar, tid);
                stsB<NT, SB>(Bs[nxt], br, tid);
                __syncthreads();
            }
        }
        __syncthreads();  // both buffers free before next nbase pass refills

        // fused epilogue: tanh(+bias) * vW, accumulate per-row sums in regs
        #pragma unroll
        for (int nt = 0; nt < NT; nt++) {
            int col = nbase + wn * (8 * NT) + nt * 8 + 2 * tg;
            float bia0 = b0[col] + b1[col];
            float bia1 = b0[col + 1] + b1[col + 1];
            float w0v = vW[col];
            float w1v = vW[col + 1];
            #pragma unroll
            for (int mt = 0; mt < 2; mt++) {
                rs[mt][0] += tanhf(acc[mt][nt][0] + bia0) * w0v
                           + tanhf(acc[mt][nt][1] + bia1) * w1v;
                rs[mt][1] += tanhf(acc[mt][nt][2] + bia0) * w0v
                           + tanhf(acc[mt][nt][3] + bia1) * w1v;
            }
        }
    }

    #pragma unroll
    for (int mt = 0; mt < 2; mt++)
        #pragma unroll
        for (int h = 0; h < 2; h++) {
            rs[mt][h] += __shfl_xor_sync(0xffffffffu, rs[mt][h], 1);
            rs[mt][h] += __shfl_xor_sync(0xffffffffu, rs[mt][h], 2);
        }

    __syncthreads();
    if (tg == 0) {
        #pragma unroll
        for (int mt = 0; mt < 2; mt++)
            #pragma unroll
            for (int h = 0; h < 2; h++)
                sred[wm * 32 + mt * 16 + h * 8 + g][wn] = rs[mt][h];
    }
    __syncthreads();
    if (tid < 64) {
        g_score[mbase + tid] = vb[0] + sred[tid][0] + sred[tid][1]
                             + sred[tid][2] + sred[tid][3];
    }
}

// ============================================================
// Kernel 2: softmax + context + embedding gather + concat (+ alpha output)
// ============================================================
__global__ __launch_bounds__(128)
void ctx_kernel(const float* __restrict__ attn, const float* __restrict__ emb,
                const int* __restrict__ inputs, float* __restrict__ out_alpha) {
    __shared__ float sc[64];
    __shared__ float wred[2][2];  // [warp][max/sum]
    const int b = blockIdx.x;
    const int tid = threadIdx.x;
    const int lane = tid & 31, wp = tid >> 5;

    // parallel softmax over 64 scores using 2 warps
    if (tid < 64) {
        float v = g_score[b * 64 + tid];
        float m = v;
        #pragma unroll
        for (int o = 16; o > 0; o >>= 1) m = fmaxf(m, __shfl_xor_sync(0xffffffffu, m, o));
        if (lane == 0) wred[wp][0] = m;
        __syncwarp();
        sc[tid] = v;
    }
    __syncthreads();
    float m = fmaxf(wred[0][0], wred[1][0]);
    if (tid < 64) {
        float e = __expf(sc[tid] - m);
        sc[tid] = e;
        float s = e;
        #pragma unroll
        for (int o = 16; o > 0; o >>= 1) s += __shfl_xor_sync(0xffffffffu, s, o);
        if (lane == 0) wred[wp][1] = s;
    }
    __syncthreads();
    float inv = 1.f / (wred[0][1] + wred[1][1]);
    if (tid < 64) {
        sc[tid] *= inv;
        if (out_alpha != nullptr) out_alpha[b * 64 + tid] = sc[tid];
    }
    __syncthreads();

    const int row = inputs[b];
    const float4* attn4 = reinterpret_cast<const float4*>(attn);
    const float4* emb4  = reinterpret_cast<const float4*>(emb);
    float4* xc4 = reinterpret_cast<float4*>(g_xc);

    float4 a = make_float4(0.f, 0.f, 0.f, 0.f);
    #pragma unroll 8
    for (int s = 0; s < 64; s++) {
        float4 t = attn4[(size_t)(b * 64 + s) * 128 + tid];
        float al = sc[s];
        a.x += t.x * al; a.y += t.y * al; a.z += t.z * al; a.w += t.w * al;
    }
    xc4[(size_t)b * 256 + 128 + tid] = a;                       // context half
    xc4[(size_t)b * 256 + tid] = emb4[(size_t)row * 128 + tid]; // embedding half
}

// ============================================================
// Kernel 4: GRU elementwise, float4-vectorized (h == 0 exact simplification)
// ============================================================
__global__ __launch_bounds__(256)
void gru_kernel(const float* __restrict__ gru_b, float* __restrict__ out_state) {
    const int i4 = blockIdx.x * blockDim.x + threadIdx.x;  // 0 .. BB*UU/4-1
    if (i4 >= BB * UU / 4) return;
    const int b = i4 / (UU / 4);
    const int j4 = i4 % (UU / 4);
    const float4* gb1 = reinterpret_cast<const float4*>(gru_b + 3 * UU);
    const float4* gg = reinterpret_cast<const float4*>(g_g);

    float4 xz = gg[(size_t)b * 384 + j4];
    float4 xr = gg[(size_t)b * 384 + 128 + j4];
    float4 xh = gg[(size_t)b * 384 + 256 + j4];
    float4 bz = gb1[j4];
    float4 brr = gb1[128 + j4];
    float4 bh = gb1[256 + j4];

    float4 st;
    {
        float z = 1.f / (1.f + __expf(-(xz.x + bz.x)));
        float r = 1.f / (1.f + __expf(-(xr.x + brr.x)));
        st.x = (1.f - z) * tanhf(xh.x + r * bh.x);
        z = 1.f / (1.f + __expf(-(xz.y + bz.y)));
        r = 1.f / (1.f + __expf(-(xr.y + brr.y)));
        st.y = (1.f - z) * tanhf(xh.y + r * bh.y);
        z = 1.f / (1.f + __expf(-(xz.z + bz.z)));
        r = 1.f / (1.f + __expf(-(xr.z + brr.z)));
        st.z = (1.f - z) * tanhf(xh.z + r * bh.z);
        z = 1.f / (1.f + __expf(-(xz.w + bz.w)));
        r = 1.f / (1.f + __expf(-(xr.w + brr.w)));
        st.w = (1.f - z) * tanhf(xh.w + r * bh.w);
    }

    reinterpret_cast<float4*>(g_state)[i4] = st;
    if (out_state != nullptr) reinterpret_cast<float4*>(out_state)[i4] = st;
}

// ============================================================
// Launch
// ============================================================
extern "C" void kernel_launch(void* const* d_in, const int* in_sizes, int n_in,
                              void* d_out, int out_size) {
    const int*   inputs = (const int*)  d_in[0];
    const float* attn   = (const float*)d_in[1];
    const float* W0     = (const float*)d_in[2];
    const float* b0     = (const float*)d_in[3];
    // d_in[4] = W1   (dead: hidden0 == 0)
    const float* b1     = (const float*)d_in[5];
    const float* vW     = (const float*)d_in[6];
    const float* vb     = (const float*)d_in[7];
    const float* emb    = (const float*)d_in[8];
    const float* gru_k  = (const float*)d_in[9];
    // d_in[10] = gru_rk (dead: h == 0)
    const float* gru_b  = (const float*)d_in[11];
    const float* dW     = (const float*)d_in[12];
    const float* db     = (const float*)d_in[13];
    const float* oW     = (const float*)d_in[14];
    const float* ob     = (const float*)d_in[15];

    float* out = (float*)d_out;
    float* out_logits = out;
    float* out_state = nullptr;
    float* out_alpha = nullptr;
    if (out_size >= BB * VV + BB * UU + BB * SS) {
        out_state = out + (size_t)BB * VV;
        out_alpha = out_state + (size_t)BB * UU;
    }

    float *p_xc, *p_g, *p_state, *p_y;
    cudaGetSymbolAddress((void**)&p_xc, g_xc);
    cudaGetSymbolAddress((void**)&p_g, g_g);
    cudaGetSymbolAddress((void**)&p_state, g_state);
    cudaGetSymbolAddress((void**)&p_y, g_y);

    // Dynamic smem sizes (bytes)
    const int smem256 = (2 * 64 * SA + 2 * 32 * 264) * 4;   // 85.5 KB
    const int smem64  = (2 * 64 * SA + 2 * 32 * 72) * 4;    // 36 KB
    const int smemSc  = smem256 + 64 * 4 * 4;               // + sred

    static bool attr_done = false;
    if (!attr_done) {
        cudaFuncSetAttribute(score_kernel, cudaFuncAttributeMaxDynamicSharedMemorySize, smemSc);
        cudaFuncSetAttribute(gemm_t<8, 264>, cudaFuncAttributeMaxDynamicSharedMemorySize, smem256);
        attr_done = true;
    }

    // 1) attention scores (tf32 mma, NT=8, pipelined, fused tanh/vW reduction)
    score_kernel<<<MM1 / 64, 256, smemSc>>>(attn, W0, b0, b1, vW, vb);
    // 2) softmax + context + embedding gather + concat (+ alpha output)
    ctx_kernel<<<BB, 128>>>(attn, emb, inputs, out_alpha);
    // 3) GRU gates GEMM: [128,1024] @ [1024,1536] + gru_b[0]  (BN=64 -> 48 blocks)
    gemm_t<2, 72><<<dim3(3 * UU / 64, BB / 64), 256, smem64>>>(p_xc, gru_k, gru_b, p_g, BB, 3 * UU, 2 * UU, 0);
    // 4) GRU nonlinearity (+ state output), float4
    gru_kernel<<<BB * UU / 4 / 256, 256>>>(gru_b, out_state);
    // 5) dense: relu([128,512] @ [512,512] + db)  (BN=64 -> 16 blocks)
    gemm_t<2, 72><<<dim3(UU / 64, BB / 64), 256, smem64>>>(p_state, dW, db, p_y, BB, UU, UU, 1);
    // 6) logits: [128,512] @ [512,32000] + ob -> output  (BN=256 -> 250 blocks)
    gemm_t<8, 264><<<dim3(VV / 256, BB / 64), 256, smem256>>>(p_y, oW, ob, out_logits, BB, VV, UU, 0);
}